// round 1
// baseline (speedup 1.0000x reference)
#include <cuda_runtime.h>
#include <cstdint>

#define NN 20000
#define EE 256000
#define HD 128
#define NRR 100

// ---------------- scratch (static device globals; no allocation) ----------------
__device__ float g_x0[NN * HD];        // embed[h]
__device__ float g_agg1[NN * HD];      // layer1 aggregation
__device__ float g_out1[NN * HD];      // layer1 output (relu)
__device__ float g_agg2[NN * 2 * HD];  // layer2 aggregation
__device__ float g_z[NN * HD];         // sampled latent
__device__ float g_hr[2048 * HD];      // decoder lhs

// ---------------- helpers ----------------
__device__ __forceinline__ unsigned long long pk2(float x, float y) {
    unsigned long long r;
    asm("mov.b64 %0, {%1, %2};" : "=l"(r) : "f"(x), "f"(y));
    return r;
}
__device__ __forceinline__ void upk2(unsigned long long p, float& x, float& y) {
    asm("mov.b64 {%0, %1}, %2;" : "=f"(x), "=f"(y) : "l"(p));
}
__device__ __forceinline__ void fma2(unsigned long long& d, unsigned long long a, unsigned long long b) {
    asm("fma.rn.f32x2 %0, %1, %2, %0;" : "+l"(d) : "l"(a), "l"(b));
}
__device__ __forceinline__ void red_add_v4(float* addr, float a, float b, float c, float d) {
    asm volatile("red.global.add.v4.f32 [%0], {%1, %2, %3, %4};"
                 :: "l"(addr), "f"(a), "f"(b), "f"(c), "f"(d) : "memory");
}
__device__ __forceinline__ float softplus_f(float x) {
    return fmaxf(x, 0.f) + log1pf(expf(-fabsf(x)));
}

// ---------------- 1) gather x0 = embed[h], zero agg buffers ----------------
__global__ __launch_bounds__(256) void init_kernel(const int* __restrict__ h,
                                                   const float* __restrict__ embed) {
    int idx = blockIdx.x * blockDim.x + threadIdx.x;  // 0 .. N*256-1
    if (idx < NN * HD) {
        g_x0[idx] = embed[h[idx >> 7] * HD + (idx & 127)];
        g_agg1[idx] = 0.f;
    }
    g_agg2[idx] = 0.f;
}

// ---------------- 2) layer1 edge messages: one warp per edge ----------------
// msg[2b+o] = sum_i x[src][2b+i] * W1[et][b][i][o]; lane l handles blocks 2l,2l+1 (cols 4l..4l+3)
__global__ __launch_bounds__(256) void edge1_kernel(const int* __restrict__ src,
                                                    const int* __restrict__ dst,
                                                    const int* __restrict__ et,
                                                    const float* __restrict__ norm,
                                                    const float* __restrict__ W1) {
    int e = (blockIdx.x * blockDim.x + threadIdx.x) >> 5;
    if (e >= EE) return;
    int lane = threadIdx.x & 31;
    int s = src[e], d = dst[e], r = et[e];
    float nrm = norm[e];
    float4 xv = ((const float4*)(g_x0 + s * HD))[lane];
    const float4* w4 = (const float4*)(W1 + r * 256 + lane * 8);
    float4 wa = __ldg(w4), wb = __ldg(w4 + 1);
    // wa = W[b=2l]: (i0o0,i0o1,i1o0,i1o1); wb = W[b=2l+1]
    float o0 = (xv.x * wa.x + xv.y * wa.z) * nrm;
    float o1 = (xv.x * wa.y + xv.y * wa.w) * nrm;
    float o2 = (xv.z * wb.x + xv.w * wb.z) * nrm;
    float o3 = (xv.z * wb.y + xv.w * wb.w) * nrm;
    red_add_v4(g_agg1 + d * HD + lane * 4, o0, o1, o2, o3);
}

// ---------------- 3) self-loop layer1: out1 = relu(agg1 + x0 @ lw1 + b1) ----------------
// block = 256 thr (8 warps), 32 rows/block, grid = 625 (exact). lane l owns cols 4l..4l+3.
__global__ __launch_bounds__(256) void selfloop1_kernel(const float* __restrict__ lw1,
                                                        const float* __restrict__ b1) {
    __shared__ float4 ws4[32][32];      // k-chunk 32 x 128 cols (16KB)
    __shared__ float xsh[8][4][33];
    int tid = threadIdx.x;
    int w = tid >> 5, lane = tid & 31;
    int row0 = blockIdx.x * 32 + w * 4;
    unsigned long long acc[4][2];
#pragma unroll
    for (int j = 0; j < 4; j++) { acc[j][0] = 0ULL; acc[j][1] = 0ULL; }
    const float4* lw4 = (const float4*)lw1;
    for (int kc = 0; kc < 4; kc++) {
#pragma unroll
        for (int it = 0; it < 4; it++) {
            int idx = tid + it * 256;
            int k = idx >> 5, c = idx & 31;
            ws4[k][c] = lw4[(kc * 32 + k) * 32 + c];
        }
#pragma unroll
        for (int j = 0; j < 4; j++)
            xsh[w][j][lane] = g_x0[(row0 + j) * HD + kc * 32 + lane];
        __syncthreads();
#pragma unroll
        for (int k = 0; k < 32; k++) {
            float4 wv = ws4[k][lane];
            unsigned long long wlo = pk2(wv.x, wv.y), whi = pk2(wv.z, wv.w);
#pragma unroll
            for (int j = 0; j < 4; j++) {
                float xv = xsh[w][j][k];
                unsigned long long x2 = pk2(xv, xv);
                fma2(acc[j][0], x2, wlo);
                fma2(acc[j][1], x2, whi);
            }
        }
        __syncthreads();
    }
    float4 bv = ((const float4*)b1)[lane];
#pragma unroll
    for (int j = 0; j < 4; j++) {
        int row = row0 + j;
        float4 av = ((const float4*)(g_agg1 + row * HD))[lane];
        float o0, o1, o2, o3;
        upk2(acc[j][0], o0, o1);
        upk2(acc[j][1], o2, o3);
        o0 = fmaxf(o0 + av.x + bv.x, 0.f);
        o1 = fmaxf(o1 + av.y + bv.y, 0.f);
        o2 = fmaxf(o2 + av.z + bv.z, 0.f);
        o3 = fmaxf(o3 + av.w + bv.w, 0.f);
        ((float4*)(g_out1 + row * HD))[lane] = make_float4(o0, o1, o2, o3);
    }
}

// ---------------- 4) layer2 edge messages (so=4): one warp per edge ----------------
// msg[4b+o] = sum_i out1[src][2b+i] * W2[et][b][i][o]; lane l handles blocks 2l,2l+1 (cols 8l..8l+7)
__global__ __launch_bounds__(256) void edge2_kernel(const int* __restrict__ src,
                                                    const int* __restrict__ dst,
                                                    const int* __restrict__ et,
                                                    const float* __restrict__ norm,
                                                    const float* __restrict__ W2) {
    int e = (blockIdx.x * blockDim.x + threadIdx.x) >> 5;
    if (e >= EE) return;
    int lane = threadIdx.x & 31;
    int s = src[e], d = dst[e], r = et[e];
    float nrm = norm[e];
    float4 xv = ((const float4*)(g_out1 + s * HD))[lane];
    const float4* w4 = (const float4*)(W2 + r * 512 + lane * 16);
    float4 wA = __ldg(w4);      // b=2l,   i=0, o0..3
    float4 wB = __ldg(w4 + 1);  // b=2l,   i=1
    float4 wC = __ldg(w4 + 2);  // b=2l+1, i=0
    float4 wD = __ldg(w4 + 3);  // b=2l+1, i=1
    float l0 = (xv.x * wA.x + xv.y * wB.x) * nrm;
    float l1 = (xv.x * wA.y + xv.y * wB.y) * nrm;
    float l2 = (xv.x * wA.z + xv.y * wB.z) * nrm;
    float l3 = (xv.x * wA.w + xv.y * wB.w) * nrm;
    float h0 = (xv.z * wC.x + xv.w * wD.x) * nrm;
    float h1 = (xv.z * wC.y + xv.w * wD.y) * nrm;
    float h2 = (xv.z * wC.z + xv.w * wD.z) * nrm;
    float h3 = (xv.z * wC.w + xv.w * wD.w) * nrm;
    float* base = g_agg2 + d * 2 * HD + lane * 8;
    red_add_v4(base, l0, l1, l2, l3);
    red_add_v4(base + 4, h0, h1, h2, h3);
}

// ---------------- 5) self-loop layer2 + gaussian sample, fused ----------------
// x2 = agg2 + out1 @ lw2 + b2 (256 cols); m = x2[:, :128], hv = x2[:,128:]
// z = m + sqrt(softplus(hv)+1e-8) * eps
// lane l owns cols {4l..4l+3} (m) and {128+4l..128+4l+3} (hv)
__global__ __launch_bounds__(256) void selfloop2_kernel(const float* __restrict__ lw2,
                                                        const float* __restrict__ b2,
                                                        const float* __restrict__ eps) {
    __shared__ float4 ws4[32][64];      // k-chunk 32 x 256 cols (32KB)
    __shared__ float xsh[8][4][33];
    int tid = threadIdx.x;
    int w = tid >> 5, lane = tid & 31;
    int row0 = blockIdx.x * 32 + w * 4;
    unsigned long long acc[4][4];
#pragma unroll
    for (int j = 0; j < 4; j++)
#pragma unroll
        for (int g = 0; g < 4; g++) acc[j][g] = 0ULL;
    const float4* lw4 = (const float4*)lw2;
    for (int kc = 0; kc < 4; kc++) {
#pragma unroll
        for (int it = 0; it < 8; it++) {
            int idx = tid + it * 256;
            int k = idx >> 6, c = idx & 63;
            ws4[k][c] = lw4[(kc * 32 + k) * 64 + c];
        }
#pragma unroll
        for (int j = 0; j < 4; j++)
            xsh[w][j][lane] = g_out1[(row0 + j) * HD + kc * 32 + lane];
        __syncthreads();
#pragma unroll
        for (int k = 0; k < 32; k++) {
            float4 w0 = ws4[k][lane];
            float4 w1 = ws4[k][32 + lane];
            unsigned long long wl0 = pk2(w0.x, w0.y), wh0 = pk2(w0.z, w0.w);
            unsigned long long wl1 = pk2(w1.x, w1.y), wh1 = pk2(w1.z, w1.w);
#pragma unroll
            for (int j = 0; j < 4; j++) {
                float xv = xsh[w][j][k];
                unsigned long long x2 = pk2(xv, xv);
                fma2(acc[j][0], x2, wl0);
                fma2(acc[j][1], x2, wh0);
                fma2(acc[j][2], x2, wl1);
                fma2(acc[j][3], x2, wh1);
            }
        }
        __syncthreads();
    }
    float4 b0 = ((const float4*)b2)[lane];
    float4 b1v = ((const float4*)b2)[32 + lane];
#pragma unroll
    for (int j = 0; j < 4; j++) {
        int row = row0 + j;
        float4 a0 = ((const float4*)(g_agg2 + row * 2 * HD))[lane];
        float4 a1 = ((const float4*)(g_agg2 + row * 2 * HD))[32 + lane];
        float m0, m1, m2, m3, v0, v1, v2, v3;
        upk2(acc[j][0], m0, m1);
        upk2(acc[j][1], m2, m3);
        upk2(acc[j][2], v0, v1);
        upk2(acc[j][3], v2, v3);
        m0 += a0.x + b0.x; m1 += a0.y + b0.y; m2 += a0.z + b0.z; m3 += a0.w + b0.w;
        v0 += a1.x + b1v.x; v1 += a1.y + b1v.y; v2 += a1.z + b1v.z; v3 += a1.w + b1v.w;
        float4 ev = ((const float4*)(eps + row * HD))[lane];
        float z0 = m0 + sqrtf(softplus_f(v0) + 1e-8f) * ev.x;
        float z1 = m1 + sqrtf(softplus_f(v1) + 1e-8f) * ev.y;
        float z2 = m2 + sqrtf(softplus_f(v2) + 1e-8f) * ev.z;
        float z3 = m3 + sqrtf(softplus_f(v3) + 1e-8f) * ev.w;
        ((float4*)(g_z + row * HD))[lane] = make_float4(z0, z1, z2, z3);
    }
}

// ---------------- 6) hr = z[head_ids] * w_rel[rel_ids] ----------------
__global__ __launch_bounds__(256) void hr_kernel(const int* __restrict__ head_ids,
                                                 const int* __restrict__ rel_ids,
                                                 const float* __restrict__ w_rel) {
    int idx = blockIdx.x * blockDim.x + threadIdx.x;  // 0 .. 2048*128-1
    int b = idx >> 7, c = idx & 127;
    g_hr[idx] = g_z[head_ids[b] * HD + c] * w_rel[rel_ids[b] * HD + c];
}

// ---------------- 7) decoder: scores = hr @ z^T  [2048 x 20000] ----------------
#define BM 128
#define BN 128
#define BK 32
__global__ __launch_bounds__(256) void decoder_kernel(float* __restrict__ out) {
    __shared__ float As[BK][BM + 4];
    __shared__ float Bs[BK][BN + 4];
    int tid = threadIdx.x;
    int row0 = blockIdx.y * BM;  // b-block (16 blocks, exact)
    int col0 = blockIdx.x * BN;  // n-block (157 blocks, last partial)
    int tr = tid >> 4, tc = tid & 15;
    unsigned long long acc[8][4];
#pragma unroll
    for (int i = 0; i < 8; i++)
#pragma unroll
        for (int p = 0; p < 4; p++) acc[i][p] = 0ULL;

    for (int kc = 0; kc < HD; kc += BK) {
#pragma unroll
        for (int it = 0; it < 4; it++) {
            int idx = tid + it * 256;      // 0..1023
            int r = idx >> 3, kq = idx & 7;
            float4 v = *(const float4*)(g_hr + (row0 + r) * HD + kc + kq * 4);
            As[kq * 4 + 0][r] = v.x; As[kq * 4 + 1][r] = v.y;
            As[kq * 4 + 2][r] = v.z; As[kq * 4 + 3][r] = v.w;
        }
#pragma unroll
        for (int it = 0; it < 4; it++) {
            int idx = tid + it * 256;
            int r = idx >> 3, kq = idx & 7;
            int n = col0 + r;
            float4 v = make_float4(0.f, 0.f, 0.f, 0.f);
            if (n < NN) v = *(const float4*)(g_z + n * HD + kc + kq * 4);
            Bs[kq * 4 + 0][r] = v.x; Bs[kq * 4 + 1][r] = v.y;
            Bs[kq * 4 + 2][r] = v.z; Bs[kq * 4 + 3][r] = v.w;
        }
        __syncthreads();
#pragma unroll
        for (int k = 0; k < BK; k++) {
            float4 a0 = *(float4*)&As[k][tr * 8];
            float4 a1 = *(float4*)&As[k][tr * 8 + 4];
            float4 bb0 = *(float4*)&Bs[k][tc * 8];
            float4 bb1 = *(float4*)&Bs[k][tc * 8 + 4];
            unsigned long long b2p[4] = {pk2(bb0.x, bb0.y), pk2(bb0.z, bb0.w),
                                         pk2(bb1.x, bb1.y), pk2(bb1.z, bb1.w)};
            float av[8] = {a0.x, a0.y, a0.z, a0.w, a1.x, a1.y, a1.z, a1.w};
#pragma unroll
            for (int i = 0; i < 8; i++) {
                unsigned long long a2 = pk2(av[i], av[i]);
                fma2(acc[i][0], a2, b2p[0]);
                fma2(acc[i][1], a2, b2p[1]);
                fma2(acc[i][2], a2, b2p[2]);
                fma2(acc[i][3], a2, b2p[3]);
            }
        }
        __syncthreads();
    }
#pragma unroll
    for (int i = 0; i < 8; i++) {
        int r = row0 + tr * 8 + i;
        int n = col0 + tc * 8;
        float o[8];
        upk2(acc[i][0], o[0], o[1]);
        upk2(acc[i][1], o[2], o[3]);
        upk2(acc[i][2], o[4], o[5]);
        upk2(acc[i][3], o[6], o[7]);
        float* orow = out + (size_t)r * NN;
        if (n + 3 < NN) *(float4*)(orow + n) = make_float4(o[0], o[1], o[2], o[3]);
        if (n + 7 < NN) *(float4*)(orow + n + 4) = make_float4(o[4], o[5], o[6], o[7]);
    }
}

// ---------------- launch ----------------
extern "C" void kernel_launch(void* const* d_in, const int* in_sizes, int n_in,
                              void* d_out, int out_size) {
    const int*   h        = (const int*)d_in[0];
    const int*   src      = (const int*)d_in[1];
    const int*   dst      = (const int*)d_in[2];
    const int*   etypes   = (const int*)d_in[3];
    const float* norm     = (const float*)d_in[4];
    const int*   head_ids = (const int*)d_in[5];
    const int*   rel_ids  = (const int*)d_in[6];
    const float* embed    = (const float*)d_in[7];
    const float* W1       = (const float*)d_in[8];
    const float* lw1      = (const float*)d_in[9];
    const float* b1       = (const float*)d_in[10];
    const float* W2       = (const float*)d_in[11];
    const float* lw2      = (const float*)d_in[12];
    const float* b2       = (const float*)d_in[13];
    const float* w_rel    = (const float*)d_in[14];
    const float* eps      = (const float*)d_in[15];
    float* out = (float*)d_out;

    init_kernel<<<(NN * 2 * HD) / 256, 256>>>(h, embed);
    edge1_kernel<<<EE / 8, 256>>>(src, dst, etypes, norm, W1);
    selfloop1_kernel<<<NN / 32, 256>>>(lw1, b1);
    edge2_kernel<<<EE / 8, 256>>>(src, dst, etypes, norm, W2);
    selfloop2_kernel<<<NN / 32, 256>>>(lw2, b2, eps);
    hr_kernel<<<(2048 * HD) / 256, 256>>>(head_ids, rel_ids, w_rel);
    dim3 dgrid((NN + BN - 1) / BN, 2048 / BM);
    decoder_kernel<<<dgrid, 256>>>(out);
}